// round 2
// baseline (speedup 1.0000x reference)
#include <cuda_runtime.h>
#include <math.h>

#define BB 64
#define CC 5
#define HH 50
#define LL 32
#define DD 300
#define QQ 200
#define VV 50000
#define NSLOT 55
#define MNEWS 2048           // BB*LL
#define MUSER 3200           // BB*HH
#define MTOT (NSLOT*MNEWS)   // 112640

// ---------------- static scratch (no allocations allowed) ----------------
__device__ float d_V[(size_t)MTOT * DD];     // gathered embeddings, later reused for GAT output G
__device__ float d_Wh[(size_t)MTOT * DD];
__device__ float d_sv[MTOT];
__device__ float d_tv[MTOT];
__device__ float d_enc[(size_t)NSLOT * BB * DD];  // per-slot encodings [slot][b][d]
__device__ float d_uV[(size_t)MUSER * DD];
__device__ float d_uWh[(size_t)MUSER * DD];
__device__ float d_us[MUSER];
__device__ float d_ut[MUSER];
__device__ float d_uG[(size_t)MUSER * DD];
__device__ float d_user[(size_t)BB * DD];

// ---------------- gather: V[slot][b*32+l] = emb[title] ----------------
__global__ void gather_kernel(const int* __restrict__ cand,
                              const int* __restrict__ clicked,
                              const float* __restrict__ emb) {
    int row  = blockIdx.x * 8 + (threadIdx.x >> 5);
    int lane = threadIdx.x & 31;
    if (row >= MTOT) return;
    int slot = row / MNEWS;
    int r    = row - slot * MNEWS;
    int b = r >> 5, l = r & 31;
    int tok = (slot < CC) ? cand[(b * CC + slot) * LL + l]
                          : clicked[(b * HH + (slot - CC)) * LL + l];
    tok = min(max(tok, 0), VV - 1);
    const float2* src = (const float2*)(emb + (size_t)tok * DD);
    float2* dst = (float2*)(d_V + (size_t)row * DD);
    for (int c = lane; c < DD / 2; c += 32) dst[c] = src[c];
}

// ---------------- generic SGEMM: C[M,300] = A[M,300] @ B[300,300] ----------------
__global__ void gemm_kernel(const float* __restrict__ A,
                            const float* __restrict__ Bm,
                            float* __restrict__ Cm, int M) {
    __shared__ __align__(16) float As[32][68];
    __shared__ __align__(16) float Bs[32][68];
    int nBase = blockIdx.x * 64;
    int mBase = blockIdx.y * 64;
    int tid = threadIdx.x;
    int ti = tid >> 4, td = tid & 15;
    float acc[4][4] = {};
    for (int kt = 0; kt < DD; kt += 32) {
        {   // A tile -> As[k][m]
            int m0 = tid >> 5;
            int k  = tid & 31;
            bool kok = (kt + k) < DD;
#pragma unroll
            for (int r = 0; r < 8; r++) {
                int m = m0 + r * 8;
                As[k][m] = kok ? A[(size_t)(mBase + m) * DD + kt + k] : 0.f;
            }
        }
        {   // B tile -> Bs[k][n]
            int k0 = tid >> 6;
            int n  = tid & 63;
            bool nok = (nBase + n) < DD;
#pragma unroll
            for (int r = 0; r < 8; r++) {
                int k = k0 + r * 4;
                Bs[k][n] = (nok && (kt + k) < DD) ? Bm[(size_t)(kt + k) * DD + nBase + n] : 0.f;
            }
        }
        __syncthreads();
#pragma unroll
        for (int kk = 0; kk < 32; kk++) {
            float4 a4 = *(const float4*)&As[kk][ti << 2];
            float4 b4 = *(const float4*)&Bs[kk][td << 2];
            float av[4] = {a4.x, a4.y, a4.z, a4.w};
            float bv[4] = {b4.x, b4.y, b4.z, b4.w};
#pragma unroll
            for (int r = 0; r < 4; r++)
#pragma unroll
                for (int c = 0; c < 4; c++) acc[r][c] += av[r] * bv[c];
        }
        __syncthreads();
    }
#pragma unroll
    for (int r = 0; r < 4; r++) {
        int m = mBase + (ti << 2) + r;
#pragma unroll
        for (int c = 0; c < 4; c++) {
            int n = nBase + (td << 2) + c;
            if (n < DD) Cm[(size_t)m * DD + n] = acc[r][c];
        }
    }
}

// ---------------- s,t per row: s = Wh.a1, t = Wh.a2 ----------------
__global__ void st_kernel(const float* __restrict__ Wh, const float* __restrict__ a,
                          float* __restrict__ sv, float* __restrict__ tv, int M) {
    int row  = blockIdx.x * 8 + (threadIdx.x >> 5);
    int lane = threadIdx.x & 31;
    if (row >= M) return;
    const float* w = Wh + (size_t)row * DD;
    float s = 0.f, t = 0.f;
    for (int c = lane; c < DD; c += 32) {
        float v = w[c];
        s += v * a[c];
        t += v * a[DD + c];
    }
#pragma unroll
    for (int o = 16; o; o >>= 1) {
        s += __shfl_xor_sync(0xffffffffu, s, o);
        t += __shfl_xor_sync(0xffffffffu, t, o);
    }
    if (!lane) { sv[row] = s; tv[row] = t; }
}

// ---------------- GAT core: G = elu( softmax_row(lrelu(s_i+t_j)) @ Wh ) ----------------
// grid: (ceil(300/64)=5 d-blocks, M/64 i-blocks, slots)
__global__ void gat_kernel(const float* __restrict__ Wh_all,
                           const float* __restrict__ sv_all,
                           const float* __restrict__ tv_all,
                           float* __restrict__ G_all, int M) {
    const float* Wh = Wh_all + (size_t)blockIdx.z * M * DD;
    const float* sv = sv_all + (size_t)blockIdx.z * M;
    const float* tv = tv_all + (size_t)blockIdx.z * M;
    float* G = G_all + (size_t)blockIdx.z * M * DD;

    int dBase = blockIdx.x * 64;
    int iBase = blockIdx.y * 64;

    __shared__ float ss[64];
    __shared__ __align__(16) float As[32][68];  // As[j][i] = exp(lrelu(s_i + t_j))
    __shared__ __align__(16) float Bs[32][68];  // Bs[j][d] = Wh[j][d]
    __shared__ float dsm[4][64];

    int tid = threadIdx.x;
    int ti = tid >> 4, td = tid & 15;
    int myi = tid & 63;        // staging row (fixed per thread)
    int j0  = tid >> 6;        // 0..3

    if (tid < 64) ss[tid] = sv[iBase + tid];
    __syncthreads();

    float acc[4][4] = {};
    float dpart = 0.f;
    float si = ss[myi];
    bool dok[4];
#pragma unroll
    for (int c = 0; c < 4; c++) dok[c] = (dBase + (td << 2) + c) < DD;

    for (int jt = 0; jt < M; jt += 32) {
        // stage A: thread covers (i=myi, j=j0+4r)
#pragma unroll
        for (int r = 0; r < 8; r++) {
            int j = j0 + r * 4;
            float x = si + tv[jt + j];
            x = (x >= 0.f) ? x : 0.2f * x;
            float av = __expf(x);
            As[j][myi] = av;
            dpart += av;
        }
        // stage B: thread covers (d=tid&63, j=(tid>>6)+4r)
        {
            int dd = tid & 63;
            bool ok = (dBase + dd) < DD;
#pragma unroll
            for (int r = 0; r < 8; r++) {
                int j = j0 + r * 4;
                Bs[j][dd] = ok ? Wh[(size_t)(jt + j) * DD + dBase + dd] : 0.f;
            }
        }
        __syncthreads();
#pragma unroll
        for (int jj = 0; jj < 32; jj++) {
            float4 a4 = *(const float4*)&As[jj][ti << 2];
            float4 b4 = *(const float4*)&Bs[jj][td << 2];
            float av[4] = {a4.x, a4.y, a4.z, a4.w};
            float bv[4] = {b4.x, b4.y, b4.z, b4.w};
#pragma unroll
            for (int r = 0; r < 4; r++)
#pragma unroll
                for (int c = 0; c < 4; c++) acc[r][c] += av[r] * bv[c];
        }
        __syncthreads();
    }

    dsm[j0][myi] = dpart;
    __syncthreads();

#pragma unroll
    for (int r = 0; r < 4; r++) {
        int i = (ti << 2) + r;
        float den = dsm[0][i] + dsm[1][i] + dsm[2][i] + dsm[3][i];
        float inv = 1.f / den;
        float* grow = G + (size_t)(iBase + i) * DD;
#pragma unroll
        for (int c = 0; c < 4; c++) {
            if (dok[c]) {
                float v = acc[r][c] * inv;
                grow[dBase + (td << 2) + c] = (v > 0.f) ? v : expm1f(v);
            }
        }
    }
}

// ---------------- additive attention ----------------
// grid: (B, slots). x rows contiguous per (slot,b): x = x_all + slot*slotM*D + b*S*D
__global__ void addattn_kernel(const float* __restrict__ x_all, int S, int slotM,
                               const float* __restrict__ lin_w,
                               const float* __restrict__ lin_b,
                               const float* __restrict__ query,
                               float* __restrict__ out) {
    extern __shared__ float xsm[];   // S * 301
    __shared__ float score[64];
    int b = blockIdx.x, slot = blockIdx.y;
    const float* x = x_all + (size_t)slot * slotM * DD + (size_t)b * S * DD;
    for (int idx = threadIdx.x; idx < S * DD; idx += blockDim.x) {
        int s = idx / DD, c = idx - s * DD;
        xsm[s * 301 + c] = x[idx];
    }
    if (threadIdx.x < 64) score[threadIdx.x] = 0.f;
    __syncthreads();

    int warp = threadIdx.x >> 5, lane = threadIdx.x & 31;
    bool two = (S > 32);
    bool has1 = two && (lane + 32) < S;
    int row1 = has1 ? (lane + 32) : 0;   // clamped: never read unallocated smem
    for (int q = warp; q < QQ; q += 8) {
        const float* lw = lin_w + (size_t)q * DD;
        float a0 = 0.f, a1 = 0.f;
        const float* x0 = &xsm[lane * 301];
        if (two) {
            const float* x1 = &xsm[row1 * 301];
#pragma unroll 4
            for (int c = 0; c < DD; c++) {
                float w = lw[c];
                a0 += x0[c] * w;
                a1 += x1[c] * w;
            }
        } else {
#pragma unroll 4
            for (int c = 0; c < DD; c++) a0 += x0[c] * lw[c];
        }
        float qv = query[q], bq = lin_b[q];
        if (lane < S) atomicAdd(&score[lane], tanhf(a0 + bq) * qv);
        if (has1) atomicAdd(&score[lane + 32], tanhf(a1 + bq) * qv);
    }
    __syncthreads();

    if (threadIdx.x < 32) {
        float v0 = (lane < S) ? score[lane] : -1e30f;
        float v1 = ((lane + 32) < S) ? score[lane + 32] : -1e30f;
        float m = fmaxf(v0, v1);
#pragma unroll
        for (int o = 16; o; o >>= 1) m = fmaxf(m, __shfl_xor_sync(0xffffffffu, m, o));
        float e0 = (lane < S) ? __expf(v0 - m) : 0.f;
        float e1 = ((lane + 32) < S) ? __expf(v1 - m) : 0.f;
        float sum = e0 + e1;
#pragma unroll
        for (int o = 16; o; o >>= 1) sum += __shfl_xor_sync(0xffffffffu, sum, o);
        float inv = 1.f / sum;
        if (lane < S) score[lane] = e0 * inv;
        if ((lane + 32) < S) score[lane + 32] = e1 * inv;
    }
    __syncthreads();

    float* o = out + (size_t)slot * BB * DD + (size_t)b * DD;
    for (int c = threadIdx.x; c < DD; c += blockDim.x) {
        float acc = 0.f;
        for (int s = 0; s < S; s++) acc += score[s] * xsm[s * 301 + c];
        o[c] = acc;
    }
}

// ---------------- reorder clicked encodings -> user GAT input ----------------
__global__ void copy_uV_kernel() {
    int row  = blockIdx.x * 8 + (threadIdx.x >> 5);
    int lane = threadIdx.x & 31;
    if (row >= MUSER) return;
    int b = row / HH, j = row - b * HH;
    const float* src = d_enc + ((size_t)(CC + j) * BB + b) * DD;
    float* dst = d_uV + (size_t)row * DD;
    for (int c = lane; c < DD; c += 32) dst[c] = src[c];
}

// ---------------- final scores: out[b,c] = cand[b,c,:].user[b,:] ----------------
__global__ void scores_kernel(float* __restrict__ out) {
    int w    = (blockIdx.x * blockDim.x + threadIdx.x) >> 5;
    int lane = threadIdx.x & 31;
    if (w >= BB * CC) return;
    int b = w / CC, c = w - b * CC;
    const float* cd = d_enc + ((size_t)c * BB + b) * DD;
    const float* u  = d_user + (size_t)b * DD;
    float acc = 0.f;
    for (int k = lane; k < DD; k += 32) acc += cd[k] * u[k];
#pragma unroll
    for (int o = 16; o; o >>= 1) acc += __shfl_xor_sync(0xffffffffu, acc, o);
    if (!lane) out[b * CC + c] = acc;
}

// ---------------- launch ----------------
extern "C" void kernel_launch(void* const* d_in, const int* in_sizes, int n_in,
                              void* d_out, int out_size) {
    // Robust size-based input mapping (stable w.r.t. dict-order or alpha-order metadata:
    // within each size class the relative order is identical in both).
    const void* by200[4] = {0, 0, 0, 0};
    const void* by600[2] = {0, 0};
    const void* by60k[2] = {0, 0};
    const void* by90k[2] = {0, 0};
    const int* cand = 0; const int* clicked = 0; const float* emb = 0;
    int n200 = 0, n600 = 0, n60k = 0, n90k = 0;
    for (int i = 0; i < n_in; i++) {
        int sz = in_sizes[i];
        if      (sz == BB * CC * LL)      cand    = (const int*)d_in[i];
        else if (sz == BB * HH * LL)      clicked = (const int*)d_in[i];
        else if (sz == VV * DD)           emb     = (const float*)d_in[i];
        else if (sz == DD * DD  && n90k < 2) by90k[n90k++] = d_in[i];
        else if (sz == 2 * DD   && n600 < 2) by600[n600++] = d_in[i];
        else if (sz == QQ * DD  && n60k < 2) by60k[n60k++] = d_in[i];
        else if (sz == QQ       && n200 < 4) by200[n200++] = d_in[i];
    }
    const float* news_W     = (const float*)by90k[0];
    const float* user_W     = (const float*)by90k[1];
    const float* news_a     = (const float*)by600[0];
    const float* user_a     = (const float*)by600[1];
    const float* news_lin_w = (const float*)by60k[0];
    const float* user_lin_w = (const float*)by60k[1];
    const float* news_lin_b = (const float*)by200[0];
    const float* news_query = (const float*)by200[1];
    const float* user_lin_b = (const float*)by200[2];
    const float* user_query = (const float*)by200[3];
    float* out = (float*)d_out;

    float *pV, *pWh, *pS, *pT, *pEnc, *pUV, *pUWh, *pUS, *pUT, *pUG, *pUser;
    cudaGetSymbolAddress((void**)&pV, d_V);
    cudaGetSymbolAddress((void**)&pWh, d_Wh);
    cudaGetSymbolAddress((void**)&pS, d_sv);
    cudaGetSymbolAddress((void**)&pT, d_tv);
    cudaGetSymbolAddress((void**)&pEnc, d_enc);
    cudaGetSymbolAddress((void**)&pUV, d_uV);
    cudaGetSymbolAddress((void**)&pUWh, d_uWh);
    cudaGetSymbolAddress((void**)&pUS, d_us);
    cudaGetSymbolAddress((void**)&pUT, d_ut);
    cudaGetSymbolAddress((void**)&pUG, d_uG);
    cudaGetSymbolAddress((void**)&pUser, d_user);

    cudaFuncSetAttribute(addattn_kernel, cudaFuncAttributeMaxDynamicSharedMemorySize, 64 * 1024);

    // 1. gather embeddings for all 55 slots
    gather_kernel<<<MTOT / 8, 256>>>(cand, clicked, emb);
    // 2. Wh = V @ news_W for all slots at once
    gemm_kernel<<<dim3(5, MTOT / 64), 256>>>(pV, news_W, pWh, MTOT);
    // 3. s, t
    st_kernel<<<MTOT / 8, 256>>>(pWh, news_a, pS, pT, MTOT);
    // 4. GAT (writes G into d_V, which is free now)
    gat_kernel<<<dim3(5, MNEWS / 64, NSLOT), 256>>>(pWh, pS, pT, pV, MNEWS);
    // 5. additive attention -> per-slot encodings
    addattn_kernel<<<dim3(BB, NSLOT), 256, 32 * 301 * 4>>>(
        pV, 32, MNEWS, news_lin_w, news_lin_b, news_query, pEnc);
    // 6. reorder clicked encodings into [b*50+h, 300]
    copy_uV_kernel<<<MUSER / 8, 256>>>();
    // 7. user Wh
    gemm_kernel<<<dim3(5, MUSER / 64), 256>>>(pUV, user_W, pUWh, MUSER);
    // 8. user s, t
    st_kernel<<<MUSER / 8, 256>>>(pUWh, user_a, pUS, pUT, MUSER);
    // 9. user GAT
    gat_kernel<<<dim3(5, MUSER / 64, 1), 256>>>(pUWh, pUS, pUT, pUG, MUSER);
    // 10. user additive attention
    addattn_kernel<<<dim3(BB, 1), 256, 50 * 301 * 4>>>(
        pUG, 50, MUSER, user_lin_w, user_lin_b, user_query, pUser);
    // 11. scores
    scores_kernel<<<40, 256>>>(out);
}